// round 6
// baseline (speedup 1.0000x reference)
#include <cuda_runtime.h>
#include <cuda_bf16.h>
#include <cuda_fp8.h>
#include <cstdint>

#define BATCH   4
#define DDIM    256
#define NPTS    4096
#define MSTRIDE 4097
#define MARGIN_F 0.5f
#define MAXDIST_F 10000.0f
#define BIG_F 1000000000.0f

// ---------------- scratch ----------------
__device__ float g_neg[(size_t)BATCH * NPTS * NPTS];          // 256 MiB
__device__ float g_pos0[BATCH][NPTS];
__device__ float g_pos1[BATCH][NPTS];
__device__ float g_mn0[BATCH][NPTS];
__device__ float g_mn1[BATCH][NPTS];
// transposed (b, n, d) operands: bf16 hi, and fp8 packed cross operands
__device__ __nv_bfloat16 g_h0[(size_t)BATCH * NPTS * DDIM];   // hi0
__device__ __nv_bfloat16 g_h1[(size_t)BATCH * NPTS * DDIM];   // hi1
__device__ uint8_t g_x0[(size_t)BATCH * NPTS * 512];          // [e4m3(hi0) | e4m3(lo0*512)]
__device__ uint8_t g_x1[(size_t)BATCH * NPTS * 512];          // [e4m3(lo1*512) | e4m3(hi1)]
__device__ float g_psum[64], g_pcnt[64], g_php[64], g_phn[64];

// ---------------- ptx helpers ----------------
__device__ __forceinline__ uint32_t smem_to_u32(const void* p) {
    uint32_t a;
    asm("{ .reg .u64 t; cvta.to.shared.u64 t, %1; cvt.u32.u64 %0, t; }"
        : "=r"(a) : "l"(p));
    return a;
}

#define LDSM_4(r0,r1,r2,r3, addr)                                               \
    asm volatile("ldmatrix.sync.aligned.m8n8.x4.shared.b16 {%0,%1,%2,%3}, [%4];"\
                 : "=r"(r0), "=r"(r1), "=r"(r2), "=r"(r3) : "r"(addr))

#define MMA_BF16(d, a, b0, b1)                                                  \
    asm volatile("mma.sync.aligned.m16n8k16.row.col.f32.bf16.bf16.f32 "         \
                 "{%0,%1,%2,%3},{%4,%5,%6,%7},{%8,%9},{%0,%1,%2,%3};"           \
                 : "+f"(d[0]), "+f"(d[1]), "+f"(d[2]), "+f"(d[3])               \
                 : "r"(a[0]), "r"(a[1]), "r"(a[2]), "r"(a[3]),                  \
                   "r"(b0), "r"(b1))

#define MMA_FP8(d, a, b0, b1)                                                   \
    asm volatile("mma.sync.aligned.m16n8k32.row.col.f32.e4m3.e4m3.f32 "         \
                 "{%0,%1,%2,%3},{%4,%5,%6,%7},{%8,%9},{%0,%1,%2,%3};"           \
                 : "+f"(d[0]), "+f"(d[1]), "+f"(d[2]), "+f"(d[3])               \
                 : "r"(a[0]), "r"(a[1]), "r"(a[2]), "r"(a[3]),                  \
                   "r"(b0), "r"(b1))

#define CP_ASYNC16(sm, gm) \
    asm volatile("cp.async.cg.shared.global [%0], [%1], 16;" :: "r"(sm), "l"(gm))
#define CP_COMMIT()  asm volatile("cp.async.commit_group;")
#define CP_WAIT3()   asm volatile("cp.async.wait_group 3;")
#define CP_WAIT2()   asm volatile("cp.async.wait_group 2;")
#define CP_WAIT1()   asm volatile("cp.async.wait_group 1;")
#define CP_WAIT0()   asm volatile("cp.async.wait_group 0;")

// ---------------- init ----------------
__global__ void init_kernel() {
    int idx = blockIdx.x * blockDim.x + threadIdx.x;
    if (idx < BATCH * NPTS) {
        ((float*)g_pos0)[idx] = 0.0f;
        ((float*)g_pos1)[idx] = 0.0f;
        ((float*)g_mn0)[idx]  = BIG_F;
        ((float*)g_mn1)[idx]  = BIG_F;
    }
}

// ---------------- prep: fp32 (b,d,n) -> (b,n,d) hi bf16 + packed fp8 -------
__device__ __forceinline__ uint8_t to_e4m3(float v) {
    __nv_fp8_e4m3 f(v);
    return *(uint8_t*)&f;
}

__global__ __launch_bounds__(256)
void prep_kernel(const float* __restrict__ d0, const float* __restrict__ d1) {
    __shared__ float s0[32][33];
    __shared__ float s1[32][33];
    const int b   = blockIdx.z;
    const int n0  = blockIdx.x * 32;
    const int dd0 = blockIdx.y * 32;
    const int tx = threadIdx.x;   // 0..31
    const int ty = threadIdx.y;   // 0..7

#pragma unroll
    for (int k = 0; k < 4; k++) {
        int d = dd0 + ty + 8 * k;
        int n = n0 + tx;
        s0[ty + 8 * k][tx] = d0[((size_t)b * DDIM + d) * NPTS + n];
        s1[ty + 8 * k][tx] = d1[((size_t)b * DDIM + d) * NPTS + n];
    }
    __syncthreads();
#pragma unroll
    for (int k = 0; k < 4; k++) {
        int n = n0 + ty + 8 * k;
        int d = dd0 + tx;
        size_t hb = ((size_t)b * NPTS + n) * DDIM + d;
        size_t xb = ((size_t)b * NPTS + n) * 512 + d;
        float v0 = s0[tx][ty + 8 * k];
        float v1 = s1[tx][ty + 8 * k];
        __nv_bfloat16 h0 = __float2bfloat16_rn(v0);
        __nv_bfloat16 h1 = __float2bfloat16_rn(v1);
        float l0 = v0 - __bfloat162float(h0);
        float l1 = v1 - __bfloat162float(h1);
        g_h0[hb] = h0;
        g_h1[hb] = h1;
        g_x0[xb]       = to_e4m3(__bfloat162float(h0));
        g_x0[xb + 256] = to_e4m3(l0 * 512.0f);
        g_x1[xb]       = to_e4m3(l1 * 512.0f);
        g_x1[xb + 256] = to_e4m3(__bfloat162float(h1));
    }
}

// ---------------------------------------------------------------------------
// pass1: hybrid fp8-cross + bf16-hi GEMM, tile 128x128, 8 warps (64x32),
// 32 k-stages of 32 bytes each, 4-deep cp.async pipeline.
//   stages 0..15 : QMMA e4m3 k32 on (X0, X1)  -> acc = 512*(cross)
//   scale acc by 1/512
//   stages 16..31: HMMA bf16 k16 on (H0, H1)  -> acc += hi0.hi1
// Fused epilogue: dist, mask row/col max atomics, neg store (round-4 proven).
// ---------------------------------------------------------------------------
#define ROWB   48            // padded row stride in smem (32B data + 16B pad)
#define TILEB  6144          // 128 rows * 48B
#define STAGEB 12288         // A tile + B tile
#define P1_SMEM (4 * STAGEB) // 49152

__global__ __launch_bounds__(256, 2)
void pass1_kernel(const float* __restrict__ mat) {
    extern __shared__ char smem_raw[];
    const uint32_t base = smem_to_u32(smem_raw);

    const int b  = blockIdx.z;
    const int i0 = blockIdx.y * 128;
    const int j0 = blockIdx.x * 128;
    const int tid = threadIdx.x;
    const int w = tid >> 5;
    const int l = tid & 31;
    const int m0w = (w & 1) * 64;
    const int n0w = (w >> 1) * 32;

    const char* Ax = (const char*)g_x0 + (size_t)b * NPTS * 512;
    const char* Bx = (const char*)g_x1 + (size_t)b * NPTS * 512;
    const char* Ah = (const char*)g_h0 + (size_t)b * NPTS * 512;
    const char* Bh = (const char*)g_h1 + (size_t)b * NPTS * 512;

    const int lrow = tid >> 1;          // 0..127
    const int lhalf = (tid & 1) * 16;   // 0 or 16

    auto load_stage = [&](int s) {
        const int st = s & 3;
        const char *Ag, *Bg;
        int koff;
        if (s < 16) { Ag = Ax; Bg = Bx; koff = s * 32; }
        else        { Ag = Ah; Bg = Bh; koff = (s - 16) * 32; }
        uint32_t da = base + st * STAGEB + lrow * ROWB + lhalf;
        uint32_t db = da + TILEB;
        CP_ASYNC16(da, Ag + (size_t)(i0 + lrow) * 512 + koff + lhalf);
        CP_ASYNC16(db, Bg + (size_t)(j0 + lrow) * 512 + koff + lhalf);
        CP_COMMIT();
    };

    float acc[4][4][4];
#pragma unroll
    for (int mi = 0; mi < 4; mi++)
#pragma unroll
        for (int nj = 0; nj < 4; nj++)
#pragma unroll
            for (int r = 0; r < 4; r++) acc[mi][nj][r] = 0.0f;

    // per-lane ldmatrix offsets (non-trans, 32B K rows, 48B stride)
    const int a_row = (l & 7) + 8 * ((l >> 3) & 1);   // + row-group by matrix
    const int a_kb  = (l >> 4) * 16;
    const int b_row = (l & 7) + 8 * (l >> 4);
    const int b_kb  = ((l >> 3) & 1) * 16;

    load_stage(0); load_stage(1); load_stage(2);

    for (int s = 0; s < 32; s++) {
        int pend = 31 - s;
        if (pend >= 2)      { CP_WAIT2(); }
        else if (pend == 1) { CP_WAIT1(); }
        else                { CP_WAIT0(); }
        __syncthreads();
        if (s + 3 < 32) load_stage(s + 3);

        const int st = s & 3;
        const uint32_t Ab = base + st * STAGEB;
        const uint32_t Bb = Ab + TILEB;

        uint32_t a[4][4], bq[2][4];
#pragma unroll
        for (int mi = 0; mi < 4; mi++) {
            uint32_t addr = Ab + (m0w + mi * 16 + a_row) * ROWB + a_kb;
            LDSM_4(a[mi][0], a[mi][1], a[mi][2], a[mi][3], addr);
        }
#pragma unroll
        for (int nb = 0; nb < 2; nb++) {
            uint32_t addr = Bb + (n0w + nb * 16 + b_row) * ROWB + b_kb;
            LDSM_4(bq[nb][0], bq[nb][1], bq[nb][2], bq[nb][3], addr);
        }

        if (s < 16) {
#pragma unroll
            for (int mi = 0; mi < 4; mi++)
#pragma unroll
                for (int nj = 0; nj < 4; nj++)
                    MMA_FP8(acc[mi][nj], a[mi],
                            bq[nj >> 1][(nj & 1) * 2], bq[nj >> 1][(nj & 1) * 2 + 1]);
        } else {
#pragma unroll
            for (int mi = 0; mi < 4; mi++)
#pragma unroll
                for (int nj = 0; nj < 4; nj++)
                    MMA_BF16(acc[mi][nj], a[mi],
                             bq[nj >> 1][(nj & 1) * 2], bq[nj >> 1][(nj & 1) * 2 + 1]);
        }

        if (s == 15) {
#pragma unroll
            for (int mi = 0; mi < 4; mi++)
#pragma unroll
                for (int nj = 0; nj < 4; nj++)
#pragma unroll
                    for (int r = 0; r < 4; r++)
                        acc[mi][nj][r] *= 0.001953125f;   // 1/512
        }
    }

    // ---- epilogue (identical structure to round 4, proven) ----
    const float* Mbase   = mat + (size_t)b * MSTRIDE * MSTRIDE;
    float*       negbase = g_neg + (size_t)b * NPTS * NPTS;

    float cmax[4][2];
#pragma unroll
    for (int nj = 0; nj < 4; nj++) { cmax[nj][0] = 0.0f; cmax[nj][1] = 0.0f; }

#pragma unroll
    for (int mi = 0; mi < 4; mi++) {
#pragma unroll
        for (int h = 0; h < 2; h++) {
            const int r = i0 + m0w + mi * 16 + (l >> 2) + h * 8;
            const float* Mr = Mbase + (size_t)r * MSTRIDE;
            float* Nr = negbase + (size_t)r * NPTS;
            float rm = 0.0f;
#pragma unroll
            for (int nj = 0; nj < 4; nj++) {
                const int cb = j0 + n0w + nj * 8 + (l & 3) * 2;
                float v0 = acc[mi][nj][h * 2 + 0];
                float v1 = acc[mi][nj][h * 2 + 1];
                float dA = fmaf(-2.0f, v0, 2.0f);
                float dB = fmaf(-2.0f, v1, 2.0f);
                float ovA = __ldg(Mr + cb);
                float ovB = __ldg(Mr + cb + 1);
                if (ovA > 0.3f) { rm = fmaxf(rm, dA); cmax[nj][0] = fmaxf(cmax[nj][0], dA); }
                if (ovB > 0.3f) { rm = fmaxf(rm, dB); cmax[nj][1] = fmaxf(cmax[nj][1], dB); }
                float nA = (ovA <= 0.0f) ? dA : MAXDIST_F;
                float nB = (ovB <= 0.0f) ? dB : MAXDIST_F;
                *(float2*)(Nr + cb) = make_float2(nA, nB);
            }
            rm = fmaxf(rm, __shfl_xor_sync(0xffffffffu, rm, 1));
            rm = fmaxf(rm, __shfl_xor_sync(0xffffffffu, rm, 2));
            if ((l & 3) == 0)
                atomicMax((int*)&g_pos0[b][r], __float_as_int(rm));
        }
    }
#pragma unroll
    for (int nj = 0; nj < 4; nj++) {
#pragma unroll
        for (int p = 0; p < 2; p++) {
            float cm = cmax[nj][p];
            cm = fmaxf(cm, __shfl_xor_sync(0xffffffffu, cm, 4));
            cm = fmaxf(cm, __shfl_xor_sync(0xffffffffu, cm, 8));
            cm = fmaxf(cm, __shfl_xor_sync(0xffffffffu, cm, 16));
            if (l < 4)
                atomicMax((int*)&g_pos1[b][j0 + n0w + nj * 8 + (l & 3) * 2 + p],
                          __float_as_int(cm));
        }
    }
}

// ---------------------------------------------------------------------------
// pass2: masked min using finalized pos0/pos1 against stored neg
// ---------------------------------------------------------------------------
__global__ __launch_bounds__(256)
void pass2_kernel() {
    const int b  = blockIdx.z;
    const int i0 = blockIdx.y * 128;
    const int j0 = blockIdx.x * 128;

    const int tid = threadIdx.x;
    const int tx = tid & 15;
    const int ty = tid >> 4;

    __shared__ float cbuf[16 * 128];

    const float* negbase = g_neg + (size_t)b * NPTS * NPTS;

    float p1[8];
#pragma unroll
    for (int c = 0; c < 8; c++) p1[c] = g_pos1[b][j0 + tx * 8 + c];

    float rmin[8], cmin[8];
#pragma unroll
    for (int r = 0; r < 8; r++) { rmin[r] = BIG_F; cmin[r] = BIG_F; }

#pragma unroll
    for (int r = 0; r < 8; r++) {
        const int i = i0 + ty * 8 + r;
        const float p0 = g_pos0[b][i];
        const float p0hi = p0 + MARGIN_F;
        const float* Nr = negbase + (size_t)i * NPTS + j0 + tx * 8;
        float4 v0 = *(const float4*)Nr;
        float4 v1 = *(const float4*)(Nr + 4);
        float nv[8] = {v0.x, v0.y, v0.z, v0.w, v1.x, v1.y, v1.z, v1.w};
#pragma unroll
        for (int c = 0; c < 8; c++) {
            float v = nv[c];
            if (v > p0 && v < p0hi)                 rmin[r] = fminf(rmin[r], v);
            if (v > p1[c] && v < p1[c] + MARGIN_F)  cmin[c] = fminf(cmin[c], v);
        }
    }

#pragma unroll
    for (int r = 0; r < 8; r++) {
#pragma unroll
        for (int s = 8; s > 0; s >>= 1)
            rmin[r] = fminf(rmin[r], __shfl_xor_sync(0xffffffffu, rmin[r], s));
    }
    if (tx == 0) {
#pragma unroll
        for (int r = 0; r < 8; r++)
            atomicMin((int*)&g_mn0[b][i0 + ty * 8 + r], __float_as_int(rmin[r]));
    }

#pragma unroll
    for (int c = 0; c < 8; c++)
        cbuf[ty * 128 + tx * 8 + c] = cmin[c];
    __syncthreads();
    if (tid < 128) {
        float m = BIG_F;
#pragma unroll
        for (int rr = 0; rr < 16; rr++)
            m = fminf(m, cbuf[rr * 128 + tid]);
        atomicMin((int*)&g_mn1[b][j0 + tid], __float_as_int(m));
    }
}

// ---------------------------------------------------------------------------
// final reduction: 64-block partial + tiny finalize
// ---------------------------------------------------------------------------
__global__ __launch_bounds__(256)
void partial_kernel() {
    const int tid = threadIdx.x;
    float sum = 0.0f, cnt = 0.0f, hp = -BIG_F, hn = BIG_F;

    for (int idx = blockIdx.x * 256 + tid; idx < 2 * BATCH * NPTS; idx += 64 * 256) {
        int b = idx >> 13;
        int r = idx & 8191;
        float pos, mn;
        if (r < NPTS) { pos = g_pos0[b][r]; mn = g_mn0[b][r]; }
        else          { pos = g_pos1[b][r - NPTS]; mn = g_mn1[b][r - NPTS]; }
        bool valid = (pos > 0.0f) && (mn < BIG_F);
        if (valid) {
            sum += fmaxf(pos - mn + 1.0f, 0.0f);
            cnt += 1.0f;
            hp = fmaxf(hp, pos);
            hn = fminf(hn, mn);
        }
    }

    __shared__ float s_sum[8], s_cnt[8], s_hp[8], s_hn[8];
#pragma unroll
    for (int s = 16; s > 0; s >>= 1) {
        sum += __shfl_xor_sync(0xffffffffu, sum, s);
        cnt += __shfl_xor_sync(0xffffffffu, cnt, s);
        hp = fmaxf(hp, __shfl_xor_sync(0xffffffffu, hp, s));
        hn = fminf(hn, __shfl_xor_sync(0xffffffffu, hn, s));
    }
    if ((tid & 31) == 0) {
        s_sum[tid >> 5] = sum; s_cnt[tid >> 5] = cnt;
        s_hp[tid >> 5] = hp;   s_hn[tid >> 5] = hn;
    }
    __syncthreads();
    if (tid == 0) {
        sum = 0.0f; cnt = 0.0f; hp = -BIG_F; hn = BIG_F;
#pragma unroll
        for (int i = 0; i < 8; i++) {
            sum += s_sum[i]; cnt += s_cnt[i];
            hp = fmaxf(hp, s_hp[i]); hn = fminf(hn, s_hn[i]);
        }
        g_psum[blockIdx.x] = sum; g_pcnt[blockIdx.x] = cnt;
        g_php[blockIdx.x] = hp;   g_phn[blockIdx.x] = hn;
    }
}

__global__ void finalize_kernel(float* __restrict__ out) {
    const int tid = threadIdx.x;   // 32 threads
    float sum = g_psum[tid] + g_psum[tid + 32];
    float cnt = g_pcnt[tid] + g_pcnt[tid + 32];
    float hp  = fmaxf(g_php[tid], g_php[tid + 32]);
    float hn  = fminf(g_phn[tid], g_phn[tid + 32]);
#pragma unroll
    for (int s = 16; s > 0; s >>= 1) {
        sum += __shfl_xor_sync(0xffffffffu, sum, s);
        cnt += __shfl_xor_sync(0xffffffffu, cnt, s);
        hp = fmaxf(hp, __shfl_xor_sync(0xffffffffu, hp, s));
        hn = fminf(hn, __shfl_xor_sync(0xffffffffu, hn, s));
    }
    if (tid == 0) {
        out[0] = sum / fmaxf(cnt, 1.0f);
        out[1] = hp;
        out[2] = hn;
    }
}

// ---------------------------------------------------------------------------
extern "C" void kernel_launch(void* const* d_in, const int* in_sizes, int n_in,
                              void* d_out, int out_size) {
    const float* desc0 = (const float*)d_in[0];
    const float* desc1 = (const float*)d_in[1];
    const float* mat   = (const float*)d_in[2];
    float* out = (float*)d_out;

    cudaFuncSetAttribute(pass1_kernel,
                         cudaFuncAttributeMaxDynamicSharedMemorySize, P1_SMEM);

    init_kernel<<<16, 1024>>>();
    prep_kernel<<<dim3(NPTS / 32, DDIM / 32, BATCH), dim3(32, 8)>>>(desc0, desc1);
    pass1_kernel<<<dim3(NPTS / 128, NPTS / 128, BATCH), 256, P1_SMEM>>>(mat);
    pass2_kernel<<<dim3(NPTS / 128, NPTS / 128, BATCH), 256>>>();
    partial_kernel<<<64, 256>>>();
    finalize_kernel<<<1, 32>>>(out);
}

// round 9
// speedup vs baseline: 1.9847x; 1.9847x over previous
#include <cuda_runtime.h>
#include <cuda_fp16.h>
#include <cstdint>

#define BATCH   4
#define DDIM    256
#define NPTS    4096
#define MSTRIDE 4097
#define MARGIN_F 0.5f
#define MAXDIST_F 10000.0f
#define BIG_F 1000000000.0f

// ---------------- scratch ----------------
__device__ __half g_negh[(size_t)BATCH * NPTS * NPTS];        // 128 MiB
__device__ float g_pos0[BATCH][NPTS];
__device__ float g_pos1[BATCH][NPTS];
__device__ float g_mn0[BATCH][NPTS];
__device__ float g_mn1[BATCH][NPTS];
// fp16 operands, (b, d, n) layout (K-major rows of n)
__device__ __half g_f0[(size_t)BATCH * DDIM * NPTS];
__device__ __half g_f1[(size_t)BATCH * DDIM * NPTS];
__device__ float g_psum[64], g_pcnt[64], g_php[64], g_phn[64];

// ---------------- ptx helpers ----------------
#define LDSM_T4(r0,r1,r2,r3, addr)                                              \
    asm volatile("ldmatrix.sync.aligned.m8n8.x4.trans.shared.b16 "              \
                 "{%0,%1,%2,%3}, [%4];"                                         \
                 : "=r"(r0), "=r"(r1), "=r"(r2), "=r"(r3) : "r"(addr))

#define MMA16816(d, a, b0, b1)                                                  \
    asm volatile("mma.sync.aligned.m16n8k16.row.col.f32.f16.f16.f32 "           \
                 "{%0,%1,%2,%3},{%4,%5,%6,%7},{%8,%9},{%0,%1,%2,%3};"           \
                 : "+f"(d[0]), "+f"(d[1]), "+f"(d[2]), "+f"(d[3])               \
                 : "r"(a[0]), "r"(a[1]), "r"(a[2]), "r"(a[3]),                  \
                   "r"(b0), "r"(b1))

#define CP_ASYNC16(sm, gm)                                                      \
    asm volatile("cp.async.cg.shared.global [%0], [%1], 16;" :: "r"(sm), "l"(gm))
#define CP_COMMIT()  asm volatile("cp.async.commit_group;")
#define CP_WAIT1()   asm volatile("cp.async.wait_group 1;")
#define CP_WAIT0()   asm volatile("cp.async.wait_group 0;")

// ---------------- init ----------------
__global__ void init_kernel() {
    int idx = blockIdx.x * blockDim.x + threadIdx.x;
    if (idx < BATCH * NPTS) {
        ((float*)g_pos0)[idx] = 0.0f;
        ((float*)g_pos1)[idx] = 0.0f;
        ((float*)g_mn0)[idx]  = BIG_F;
        ((float*)g_mn1)[idx]  = BIG_F;
    }
}

// ---------------- prep: fp32 -> fp16, same (b,d,n) layout ----------------
__global__ __launch_bounds__(256)
void prep_kernel(const float* __restrict__ d0, const float* __restrict__ d1) {
    size_t i = ((size_t)blockIdx.x * 256 + threadIdx.x) * 4;
    float4 v0 = *(const float4*)(d0 + i);
    float4 v1 = *(const float4*)(d1 + i);
    __half2 a0 = __floats2half2_rn(v0.x, v0.y);
    __half2 a1 = __floats2half2_rn(v0.z, v0.w);
    __half2 b0 = __floats2half2_rn(v1.x, v1.y);
    __half2 b1 = __floats2half2_rn(v1.z, v1.w);
    *(__half2*)(g_f0 + i)     = a0;
    *(__half2*)(g_f0 + i + 2) = a1;
    *(__half2*)(g_f1 + i)     = b0;
    *(__half2*)(g_f1 + i + 2) = b1;
}

// ---------------------------------------------------------------------------
// pass1: fp16 HMMA GEMM K=256, tile 128x128, 8 warps (64x32), BK=16,
// 3-stage cp.async pipeline. Fused epilogue: dist, mask row/col max atomics,
// fp16 neg store.  (Structure proven in round 4.)
// ---------------------------------------------------------------------------
#define LDA 136
#define NCH 16    // 256 / 16

__global__ __launch_bounds__(256, 2)
void pass1_kernel(const float* __restrict__ mat) {
    const int b  = blockIdx.z;
    const int i0 = blockIdx.y * 128;
    const int j0 = blockIdx.x * 128;

    __shared__ __half As[3][16][LDA];
    __shared__ __half Bs[3][16][LDA];

    const int tid = threadIdx.x;
    const int w   = tid >> 5;
    const int l   = tid & 31;
    const int m0w = (w & 1) * 64;
    const int n0w = (w >> 1) * 32;

    const __half* Ag0 = g_f0 + (size_t)b * DDIM * NPTS;
    const __half* Bg0 = g_f1 + (size_t)b * DDIM * NPTS;

    const int lrow = tid >> 4;          // 0..15
    const int lcol = (tid & 15) * 8;    // half elems

    auto load_stage = [&](int kc) {
        int st = kc % 3;
        int kk = kc * 16;
        const __half* Ag = Ag0 + (size_t)(kk + lrow) * NPTS + i0 + lcol;
        const __half* Bg = Bg0 + (size_t)(kk + lrow) * NPTS + j0 + lcol;
        uint32_t sa = (uint32_t)__cvta_generic_to_shared(&As[st][lrow][lcol]);
        uint32_t sb = (uint32_t)__cvta_generic_to_shared(&Bs[st][lrow][lcol]);
        CP_ASYNC16(sa, Ag);
        CP_ASYNC16(sb, Bg);
        CP_COMMIT();
    };

    float acc[4][4][4];
#pragma unroll
    for (int mi = 0; mi < 4; mi++)
#pragma unroll
        for (int nj = 0; nj < 4; nj++)
#pragma unroll
            for (int r = 0; r < 4; r++) acc[mi][nj][r] = 0.0f;

    const int a_row = ((l >> 4) << 3) + (l & 7);
    const int a_col = ((l >> 3) & 1) * 8;
    const int b_row = (((l >> 3) & 1) << 3) + (l & 7);
    const int b_col = (l >> 4) * 8;

    load_stage(0);
    load_stage(1);

    for (int kc = 0; kc < NCH; kc++) {
        if (kc + 1 < NCH) { CP_WAIT1(); } else { CP_WAIT0(); }
        __syncthreads();
        if (kc + 2 < NCH) load_stage(kc + 2);

        const int st = kc % 3;
        uint32_t a[4][4];
#pragma unroll
        for (int mi = 0; mi < 4; mi++) {
            uint32_t addr = (uint32_t)__cvta_generic_to_shared(
                &As[st][a_row][m0w + mi * 16 + a_col]);
            LDSM_T4(a[mi][0], a[mi][1], a[mi][2], a[mi][3], addr);
        }
        uint32_t bq[2][4];
#pragma unroll
        for (int nb = 0; nb < 2; nb++) {
            uint32_t addr = (uint32_t)__cvta_generic_to_shared(
                &Bs[st][b_row][n0w + nb * 16 + b_col]);
            LDSM_T4(bq[nb][0], bq[nb][1], bq[nb][2], bq[nb][3], addr);
        }
#pragma unroll
        for (int mi = 0; mi < 4; mi++)
#pragma unroll
            for (int nj = 0; nj < 4; nj++)
                MMA16816(acc[mi][nj], a[mi], bq[nj >> 1][(nj & 1) * 2],
                         bq[nj >> 1][(nj & 1) * 2 + 1]);
    }

    // ---- epilogue ----
    const float* Mbase   = mat + (size_t)b * MSTRIDE * MSTRIDE;
    __half*      negbase = g_negh + (size_t)b * NPTS * NPTS;

    float cmax[4][2];
#pragma unroll
    for (int nj = 0; nj < 4; nj++) { cmax[nj][0] = 0.0f; cmax[nj][1] = 0.0f; }

#pragma unroll
    for (int mi = 0; mi < 4; mi++) {
#pragma unroll
        for (int h = 0; h < 2; h++) {
            const int r = i0 + m0w + mi * 16 + (l >> 2) + h * 8;
            const float* Mr = Mbase + (size_t)r * MSTRIDE;
            __half* Nr = negbase + (size_t)r * NPTS;
            float rm = 0.0f;
#pragma unroll
            for (int nj = 0; nj < 4; nj++) {
                const int cb = j0 + n0w + nj * 8 + (l & 3) * 2;
                float v0 = acc[mi][nj][h * 2 + 0];
                float v1 = acc[mi][nj][h * 2 + 1];
                float dA = fmaf(-2.0f, v0, 2.0f);
                float dB = fmaf(-2.0f, v1, 2.0f);
                float ovA = __ldg(Mr + cb);
                float ovB = __ldg(Mr + cb + 1);
                if (ovA > 0.3f) { rm = fmaxf(rm, dA); cmax[nj][0] = fmaxf(cmax[nj][0], dA); }
                if (ovB > 0.3f) { rm = fmaxf(rm, dB); cmax[nj][1] = fmaxf(cmax[nj][1], dB); }
                float nA = (ovA <= 0.0f) ? dA : MAXDIST_F;
                float nB = (ovB <= 0.0f) ? dB : MAXDIST_F;
                *(__half2*)(Nr + cb) = __floats2half2_rn(nA, nB);
            }
            rm = fmaxf(rm, __shfl_xor_sync(0xffffffffu, rm, 1));
            rm = fmaxf(rm, __shfl_xor_sync(0xffffffffu, rm, 2));
            if ((l & 3) == 0)
                atomicMax((int*)&g_pos0[b][r], __float_as_int(rm));
        }
    }
#pragma unroll
    for (int nj = 0; nj < 4; nj++) {
#pragma unroll
        for (int p = 0; p < 2; p++) {
            float cm = cmax[nj][p];
            cm = fmaxf(cm, __shfl_xor_sync(0xffffffffu, cm, 4));
            cm = fmaxf(cm, __shfl_xor_sync(0xffffffffu, cm, 8));
            cm = fmaxf(cm, __shfl_xor_sync(0xffffffffu, cm, 16));
            if (l < 4)
                atomicMax((int*)&g_pos1[b][j0 + n0w + nj * 8 + (l & 3) * 2 + p],
                          __float_as_int(cm));
        }
    }
}

// ---------------------------------------------------------------------------
// pass2: masked min on fp16 neg, half2 SIMD window checks
// ---------------------------------------------------------------------------
__global__ __launch_bounds__(256)
void pass2_kernel() {
    const int b  = blockIdx.z;
    const int i0 = blockIdx.y * 128;
    const int j0 = blockIdx.x * 128;

    const int tid = threadIdx.x;
    const int tx = tid & 15;
    const int ty = tid >> 4;

    __shared__ float cbuf[16 * 128];

    const __half* negbase = g_negh + (size_t)b * NPTS * NPTS;
    const __half2 one2 = __float2half2_rn(1.0f);
    const __half2 big2 = __float2half2_rn(30000.0f);
    const __half2 mar2 = __float2half2_rn(MARGIN_F);

    // column window bounds (4 half2 pairs covering 8 cols)
    __half2 p1lo[4], p1hi[4];
#pragma unroll
    for (int c2 = 0; c2 < 4; c2++) {
        float a = g_pos1[b][j0 + tx * 8 + 2 * c2];
        float c = g_pos1[b][j0 + tx * 8 + 2 * c2 + 1];
        p1lo[c2] = __floats2half2_rn(a, c);
        p1hi[c2] = __hadd2(p1lo[c2], mar2);
    }

    __half2 rmin2[8], cmin2[4];
#pragma unroll
    for (int r = 0; r < 8; r++) rmin2[r] = big2;
#pragma unroll
    for (int c2 = 0; c2 < 4; c2++) cmin2[c2] = big2;

#pragma unroll
    for (int r = 0; r < 8; r++) {
        const int i = i0 + ty * 8 + r;
        const float p0 = g_pos0[b][i];
        const __half2 p02  = __float2half2_rn(p0);
        const __half2 phi2 = __float2half2_rn(p0 + MARGIN_F);
        const __half* Nr = negbase + (size_t)i * NPTS + j0 + tx * 8;
        float4 raw = *(const float4*)Nr;        // 8 halfs
        __half2 v[4];
        v[0] = *(__half2*)&raw.x; v[1] = *(__half2*)&raw.y;
        v[2] = *(__half2*)&raw.z; v[3] = *(__half2*)&raw.w;
#pragma unroll
        for (int c2 = 0; c2 < 4; c2++) {
            __half2 ok = __hmul2(__hgt2(v[c2], p02), __hlt2(v[c2], phi2));
            __half2 cand = __hfma2(__hsub2(one2, ok), big2, v[c2]);
            rmin2[r] = __hmin2(rmin2[r], cand);

            __half2 okc = __hmul2(__hgt2(v[c2], p1lo[c2]), __hlt2(v[c2], p1hi[c2]));
            __half2 candc = __hfma2(__hsub2(one2, okc), big2, v[c2]);
            cmin2[c2] = __hmin2(cmin2[c2], candc);
        }
    }

    // row min: scalar + shfl over 16 tx lanes
#pragma unroll
    for (int r = 0; r < 8; r++) {
        float m = fminf(__low2float(rmin2[r]), __high2float(rmin2[r]));
#pragma unroll
        for (int s = 8; s > 0; s >>= 1)
            m = fminf(m, __shfl_xor_sync(0xffffffffu, m, s));
        if (tx == 0) {
            float mv = (m < 5000.0f) ? m : BIG_F;
            atomicMin((int*)&g_mn0[b][i0 + ty * 8 + r], __float_as_int(mv));
        }
    }

    // col min via smem
#pragma unroll
    for (int c2 = 0; c2 < 4; c2++) {
        cbuf[ty * 128 + tx * 8 + 2 * c2]     = __low2float(cmin2[c2]);
        cbuf[ty * 128 + tx * 8 + 2 * c2 + 1] = __high2float(cmin2[c2]);
    }
    __syncthreads();
    if (tid < 128) {
        float m = BIG_F;
#pragma unroll
        for (int rr = 0; rr < 16; rr++)
            m = fminf(m, cbuf[rr * 128 + tid]);
        float mv = (m < 5000.0f) ? m : BIG_F;
        atomicMin((int*)&g_mn1[b][j0 + tid], __float_as_int(mv));
    }
}

// ---------------------------------------------------------------------------
// final reduction: 64-block partial + tiny finalize
// ---------------------------------------------------------------------------
__global__ __launch_bounds__(256)
void partial_kernel() {
    const int tid = threadIdx.x;
    float sum = 0.0f, cnt = 0.0f, hp = -BIG_F, hn = BIG_F;

    for (int idx = blockIdx.x * 256 + tid; idx < 2 * BATCH * NPTS; idx += 64 * 256) {
        int b = idx >> 13;
        int r = idx & 8191;
        float pos, mn;
        if (r < NPTS) { pos = g_pos0[b][r]; mn = g_mn0[b][r]; }
        else          { pos = g_pos1[b][r - NPTS]; mn = g_mn1[b][r - NPTS]; }
        bool valid = (pos > 0.0f) && (mn < BIG_F);
        if (valid) {
            sum += fmaxf(pos - mn + 1.0f, 0.0f);
            cnt += 1.0f;
            hp = fmaxf(hp, pos);
            hn = fminf(hn, mn);
        }
    }

    __shared__ float s_sum[8], s_cnt[8], s_hp[8], s_hn[8];
#pragma unroll
    for (int s = 16; s > 0; s >>= 1) {
        sum += __shfl_xor_sync(0xffffffffu, sum, s);
        cnt += __shfl_xor_sync(0xffffffffu, cnt, s);
        hp = fmaxf(hp, __shfl_xor_sync(0xffffffffu, hp, s));
        hn = fminf(hn, __shfl_xor_sync(0xffffffffu, hn, s));
    }
    if ((tid & 31) == 0) {
        s_sum[tid >> 5] = sum; s_cnt[tid >> 5] = cnt;
        s_hp[tid >> 5] = hp;   s_hn[tid >> 5] = hn;
    }
    __syncthreads();
    if (tid == 0) {
        sum = 0.0f; cnt = 0.0f; hp = -BIG_F; hn = BIG_F;
#pragma unroll
        for (int i = 0; i < 8; i++) {
            sum += s_sum[i]; cnt += s_cnt[i];
            hp = fmaxf(hp, s_hp[i]); hn = fminf(hn, s_hn[i]);
        }
        g_psum[blockIdx.x] = sum; g_pcnt[blockIdx.x] = cnt;
        g_php[blockIdx.x] = hp;   g_phn[blockIdx.x] = hn;
    }
}

__global__ void finalize_kernel(float* __restrict__ out) {
    const int tid = threadIdx.x;   // 32 threads
    float sum = g_psum[tid] + g_psum[tid + 32];
    float cnt = g_pcnt[tid] + g_pcnt[tid + 32];
    float hp  = fmaxf(g_php[tid], g_php[tid + 32]);
    float hn  = fminf(g_phn[tid], g_phn[tid + 32]);
#pragma unroll
    for (int s = 16; s > 0; s >>= 1) {
        sum += __shfl_xor_sync(0xffffffffu, sum, s);
        cnt += __shfl_xor_sync(0xffffffffu, cnt, s);
        hp = fmaxf(hp, __shfl_xor_sync(0xffffffffu, hp, s));
        hn = fminf(hn, __shfl_xor_sync(0xffffffffu, hn, s));
    }
    if (tid == 0) {
        out[0] = sum / fmaxf(cnt, 1.0f);
        out[1] = hp;
        out[2] = hn;
    }
}

// ---------------------------------------------------------------------------
extern "C" void kernel_launch(void* const* d_in, const int* in_sizes, int n_in,
                              void* d_out, int out_size) {
    const float* desc0 = (const float*)d_in[0];
    const float* desc1 = (const float*)d_in[1];
    const float* mat   = (const float*)d_in[2];
    float* out = (float*)d_out;

    init_kernel<<<16, 1024>>>();
    prep_kernel<<<4096, 256>>>(desc0, desc1);
    pass1_kernel<<<dim3(NPTS / 128, NPTS / 128, BATCH), 256>>>(mat);
    pass2_kernel<<<dim3(NPTS / 128, NPTS / 128, BATCH), 256>>>();
    partial_kernel<<<64, 256>>>();
    finalize_kernel<<<1, 32>>>(out);
}